// round 13
// baseline (speedup 1.0000x reference)
#include <cuda_runtime.h>
#include <cfloat>

#define BB 8
#define CC 64
#define NN 2048
#define MM 2048
#define KSEL 614

typedef unsigned long long ull;

__device__ float g_pd[(size_t)BB * NN * MM];
__device__ float g_xx[BB * NN];
__device__ float g_yy[BB * MM];
__device__ float g_rowp_m[16 * BB * NN];
__device__ float g_rowp_z[16 * BB * NN];
__device__ float g_colp_m[32 * BB * MM];
__device__ float g_colp_z[32 * BB * MM];
__device__ float g_rowmax[BB * NN];
__device__ float g_rowinvZ[BB * NN];
__device__ float g_colmax[BB * MM];
__device__ float g_colinvZ[BB * MM];
__device__ float g_csp[32 * BB * MM];
__device__ float g_rsp[2 * BB * NN];
__device__ unsigned char g_maskSrc[BB * NN];
__device__ unsigned char g_maskTgt[BB * MM];
__device__ float g_valInlier[BB * NN];

// ---------------- f32x2 helpers ----------------
__device__ __forceinline__ ull pack2(float x, float y) {
    ull r; asm("mov.b64 %0, {%1, %2};" : "=l"(r) : "f"(x), "f"(y)); return r;
}
__device__ __forceinline__ float2 unpack2(ull v) {
    float2 r; asm("mov.b64 {%0, %1}, %2;" : "=f"(r.x), "=f"(r.y) : "l"(v)); return r;
}
#define FMA2(d, a, b) asm("fma.rn.f32x2 %0, %1, %2, %0;" : "+l"(d) : "l"(a), "l"(b))

// ---------------- squared norms (one tensor per launch) ----------------
__global__ void sqnorm_kernel(const float* __restrict__ emb, int which) {
    int idx = blockIdx.x * blockDim.x + threadIdx.x;
    if (idx >= BB * 2048) return;
    int b = idx >> 11, p = idx & 2047;
    const float* e = emb + (size_t)b * CC * 2048 + p;
    float s = 0.f;
#pragma unroll
    for (int c = 0; c < CC; c++) { float v = e[(size_t)c * 2048]; s += v * v; }
    if (which) g_yy[idx] = s; else g_xx[idx] = s;
}

// ---------------- no-op spacer (keeps GEMM at profiled launch slot 3) -------------
__global__ void nop_kernel() {}

// ---------------- GEMM (FFMA2): 64(n) x 128(m) tile, 4x8/thread, 3 CTAs/SM --------
__global__ __launch_bounds__(256, 3) void gemm_pd_kernel(const float* __restrict__ src,
                                                         const float* __restrict__ tgt) {
    __shared__ __align__(16) char sbuf[16384];
    ull   (*As2)[64]  = (ull(*)[64])sbuf;                // 16 x 64 ull = 8KB
    float (*Bs)[128]  = (float(*)[128])(sbuf + 8192);    // 16 x 128 f  = 8KB

    int b = blockIdx.z;
    int m0 = blockIdx.x * 128, n0 = blockIdx.y * 64;
    int tid = threadIdx.x;
    int tx = tid & 15, ty = tid >> 4;                    // tx: m-group, ty: n-group (0..15)
    const float* Sg = src + (size_t)b * CC * NN + n0;
    const float* Tg = tgt + (size_t)b * CC * MM + m0;

    int lk = tid >> 4;                                   // k-row for loads
    int la = (tid & 15) * 4;                             // A col group
    int lb = (tid & 15) * 8;                             // B col group

    ull acc[4][4];
#pragma unroll
    for (int j = 0; j < 4; j++)
#pragma unroll
        for (int i = 0; i < 4; i++) acc[j][i] = 0ull;

    for (int s = 0; s < 4; s++) {
        int kk = 16 * s;
        {
            float4 a4 = *(const float4*)&Sg[(size_t)(kk + lk) * NN + la];
            float4 rb0 = *(const float4*)&Tg[(size_t)(kk + lk) * MM + lb];
            float4 rb1 = *(const float4*)&Tg[(size_t)(kk + lk) * MM + lb + 4];
            ull* ar = &As2[lk][la];
            ar[0] = pack2(a4.x, a4.x); ar[1] = pack2(a4.y, a4.y);
            ar[2] = pack2(a4.z, a4.z); ar[3] = pack2(a4.w, a4.w);
            *(float4*)&Bs[lk][lb] = rb0;
            *(float4*)&Bs[lk][lb + 4] = rb1;
        }
        __syncthreads();
#pragma unroll
        for (int k = 0; k < 16; k++) {
            ull a[4];
            *(ulonglong2*)&a[0] = *(const ulonglong2*)&As2[k][ty * 4];
            *(ulonglong2*)&a[2] = *(const ulonglong2*)&As2[k][ty * 4 + 2];
            ull bv[4];
            *(ulonglong2*)&bv[0] = *(const ulonglong2*)&Bs[k][tx * 8];
            *(ulonglong2*)&bv[2] = *(const ulonglong2*)&Bs[k][tx * 8 + 4];
#pragma unroll
            for (int j = 0; j < 4; j++) {
                FMA2(acc[j][0], a[j], bv[0]);
                FMA2(acc[j][1], a[j], bv[1]);
                FMA2(acc[j][2], a[j], bv[2]);
                FMA2(acc[j][3], a[j], bv[3]);
            }
        }
        __syncthreads();
    }

    // ---- epilogue: finalize pd, write, fused TRUE row/col stat partials ----
    int cg = m0 + tx * 8;
    float yv[8], xr[4];
    *(float4*)&yv[0] = *(const float4*)&g_yy[b * MM + cg];
    *(float4*)&yv[4] = *(const float4*)&g_yy[b * MM + cg + 4];
#pragma unroll
    for (int j = 0; j < 4; j++) xr[j] = g_xx[b * NN + n0 + ty * 4 + j];

    float cm[8];
#pragma unroll
    for (int i = 0; i < 8; i++) cm[i] = -FLT_MAX;
#pragma unroll
    for (int j = 0; j < 4; j++) {
#pragma unroll
        for (int i = 0; i < 4; i++) {
            float2 p = unpack2(acc[j][i]);
            cm[2 * i]     = fmaxf(cm[2 * i],     2.f * p.x - xr[j] - yv[2 * i]);
            cm[2 * i + 1] = fmaxf(cm[2 * i + 1], 2.f * p.y - xr[j] - yv[2 * i + 1]);
        }
    }

    float colz[8];
#pragma unroll
    for (int i = 0; i < 8; i++) colz[i] = 0.f;
#pragma unroll
    for (int j = 0; j < 4; j++) {
        float fr[8];
#pragma unroll
        for (int i = 0; i < 4; i++) {
            float2 p = unpack2(acc[j][i]);
            fr[2 * i]     = 2.f * p.x - xr[j] - yv[2 * i];
            fr[2 * i + 1] = 2.f * p.y - xr[j] - yv[2 * i + 1];
        }
        int n = n0 + ty * 4 + j;
        float* prow = g_pd + (size_t)(b * NN + n) * MM;
        *(float4*)&prow[cg]     = make_float4(fr[0], fr[1], fr[2], fr[3]);
        *(float4*)&prow[cg + 4] = make_float4(fr[4], fr[5], fr[6], fr[7]);

        float rmx = fr[0];
#pragma unroll
        for (int i = 1; i < 8; i++) rmx = fmaxf(rmx, fr[i]);
#pragma unroll
        for (int o = 1; o < 16; o <<= 1) rmx = fmaxf(rmx, __shfl_xor_sync(0xffffffffu, rmx, o));
        float rz = 0.f;
#pragma unroll
        for (int i = 0; i < 8; i++) rz += __expf(fr[i] - rmx);
#pragma unroll
        for (int o = 1; o < 16; o <<= 1) rz += __shfl_xor_sync(0xffffffffu, rz, o);
        if (tx == 0) {
            g_rowp_m[blockIdx.x * (BB * NN) + b * NN + n] = rmx;
            g_rowp_z[blockIdx.x * (BB * NN) + b * NN + n] = rz;
        }
#pragma unroll
        for (int i = 0; i < 8; i++) colz[i] += __expf(fr[i] - cm[i]);
    }

    __syncthreads();
    float* sm_m = (float*)sbuf;            // [16][128] = 8KB
    float* sm_z = (float*)(sbuf + 8192);   // 8KB
#pragma unroll
    for (int i = 0; i < 8; i++) {
        sm_m[ty * 128 + tx * 8 + i] = cm[i];
        sm_z[ty * 128 + tx * 8 + i] = colz[i];
    }
    __syncthreads();
    if (tid < 128) {
        int c = tid;
        float M = -FLT_MAX;
#pragma unroll
        for (int t = 0; t < 16; t++) M = fmaxf(M, sm_m[t * 128 + c]);
        float Z = 0.f;
#pragma unroll
        for (int t = 0; t < 16; t++) Z += sm_z[t * 128 + c] * __expf(sm_m[t * 128 + c] - M);
        g_colp_m[blockIdx.y * (BB * MM) + b * MM + m0 + c] = M;
        g_colp_z[blockIdx.y * (BB * MM) + b * MM + m0 + c] = Z;
    }
}

// ---------------- merge stat partials ----------------
__global__ void merge_stats_kernel() {
    int idx = blockIdx.x * blockDim.x + threadIdx.x;
    if (idx >= BB * 2048) return;
    if (blockIdx.y == 0) {
        float M = -FLT_MAX, Z = 0.f;
#pragma unroll
        for (int t = 0; t < 16; t++) {
            float m2 = g_rowp_m[t * (BB * NN) + idx], z2 = g_rowp_z[t * (BB * NN) + idx];
            float nm = fmaxf(M, m2);
            Z = Z * __expf(M - nm) + z2 * __expf(m2 - nm);
            M = nm;
        }
        g_rowmax[idx] = M; g_rowinvZ[idx] = 1.f / Z;
    } else {
        float M = -FLT_MAX, Z = 0.f;
#pragma unroll
        for (int t = 0; t < 32; t++) {
            float m2 = g_colp_m[t * (BB * MM) + idx], z2 = g_colp_z[t * (BB * MM) + idx];
            float nm = fmaxf(M, m2);
            Z = Z * __expf(M - nm) + z2 * __expf(m2 - nm);
            M = nm;
        }
        g_colmax[idx] = M; g_colinvZ[idx] = 1.f / Z;
    }
}

// ---------------- fused colSum + rowSum pass: 1024 cols x 64 rows, 512 blocks ------
__global__ __launch_bounds__(256) void cs_rs_kernel() {
    __shared__ float s_rm[64], s_riz[64];
    __shared__ float rs_w[8][64];
    int b = blockIdx.z, rt = blockIdx.y, ct = blockIdx.x;
    int tid = threadIdx.x, lane = tid & 31, warp = tid >> 5;
    int m = ct * 1024 + tid * 4;
    int r0 = rt * 64;
    if (tid < 64) {
        s_rm[tid]  = g_rowmax[b * NN + r0 + tid];
        s_riz[tid] = g_rowinvZ[b * NN + r0 + tid];
    }
    float4 cmx = *(const float4*)&g_colmax[b * MM + m];
    float4 ciz = *(const float4*)&g_colinvZ[b * MM + m];
    __syncthreads();
    float cs0 = 0.f, cs1 = 0.f, cs2 = 0.f, cs3 = 0.f;
    const float* base = g_pd + ((size_t)(b * NN + r0)) * MM + m;
    for (int g = 0; g < 16; g++) {
        float rs[4];
#pragma unroll
        for (int u = 0; u < 4; u++) {
            int n = g * 4 + u;
            float4 v = *(const float4*)(base + (size_t)n * MM);
            float rm = s_rm[n], riz = s_riz[n];
            cs0 += __expf(v.x - rm) * riz; cs1 += __expf(v.y - rm) * riz;
            cs2 += __expf(v.z - rm) * riz; cs3 += __expf(v.w - rm) * riz;
            rs[u] = __expf(v.x - cmx.x) * ciz.x + __expf(v.y - cmx.y) * ciz.y
                  + __expf(v.z - cmx.z) * ciz.z + __expf(v.w - cmx.w) * ciz.w;
        }
#pragma unroll
        for (int o = 16; o > 0; o >>= 1) {
            rs[0] += __shfl_xor_sync(0xffffffffu, rs[0], o);
            rs[1] += __shfl_xor_sync(0xffffffffu, rs[1], o);
            rs[2] += __shfl_xor_sync(0xffffffffu, rs[2], o);
            rs[3] += __shfl_xor_sync(0xffffffffu, rs[3], o);
        }
        if (lane == 0) {
            rs_w[warp][g * 4]     = rs[0];
            rs_w[warp][g * 4 + 1] = rs[1];
            rs_w[warp][g * 4 + 2] = rs[2];
            rs_w[warp][g * 4 + 3] = rs[3];
        }
    }
    __syncthreads();
    *(float4*)&g_csp[rt * (BB * MM) + b * MM + m] = make_float4(cs0, cs1, cs2, cs3);
    if (tid < 64) {
        float s = 0.f;
#pragma unroll
        for (int q = 0; q < 8; q++) s += rs_w[q][tid];
        g_rsp[ct * (BB * NN) + b * NN + r0 + tid] = s;
    }
}

// ---------------- per-batch k-th smallest ----------------
__global__ __launch_bounds__(256) void thresh_kernel(float* __restrict__ outMaskTgt,
                                                     float* __restrict__ outMaskSrc) {
    __shared__ float s[2048];
    __shared__ float vals[2048];
    int b = blockIdx.x, which = blockIdx.y, tid = threadIdx.x;
    if (which == 0) {
        for (int i = tid; i < 2048; i += 256) {
            float v = 0.f;
#pragma unroll
            for (int t = 0; t < 32; t++) v += g_csp[t * (BB * MM) + b * MM + i];
            vals[i] = v; s[i] = v;
        }
    } else {
        for (int i = tid; i < 2048; i += 256) {
            float v = g_rsp[b * NN + i] + g_rsp[BB * NN + b * NN + i];
            vals[i] = v; s[i] = v;
        }
    }
    __syncthreads();
    for (int k = 2; k <= 2048; k <<= 1) {
        for (int j = k >> 1; j > 0; j >>= 1) {
            for (int t = tid; t < 2048; t += 256) {
                int ixj = t ^ j;
                if (ixj > t) {
                    float a = s[t], c = s[ixj];
                    bool up = ((t & k) == 0);
                    if (up ? (a > c) : (a < c)) { s[t] = c; s[ixj] = a; }
                }
            }
            __syncthreads();
        }
    }
    float thresh = s[KSEL - 1];
    unsigned char* mb = which ? (g_maskSrc + b * 2048) : (g_maskTgt + b * 2048);
    float* mf = (which ? outMaskSrc : outMaskTgt) + b * 2048;
    for (int i = tid; i < 2048; i += 256) {
        bool mk = vals[i] < thresh;
        mb[i] = (unsigned char)mk;
        mf[i] = mk ? 1.0f : 0.0f;
    }
}

// ---------------- final row pass (R8 form) ----------------
__global__ __launch_bounds__(256) void final_row_kernel(const float* __restrict__ tgt,
                                                        float* __restrict__ outCorr) {
    __shared__ float sm[8][4];
    int row = blockIdx.x;
    int b = row >> 11, n = row & 2047;
    int tid = threadIdx.x, lane = tid & 31, w = tid >> 5;
    const float* p = g_pd + (size_t)row * MM;
    float rm = g_rowmax[row], riz = g_rowinvZ[row];
    int msrc = g_maskSrc[row];
    const unsigned char* mtgt = g_maskTgt + b * MM;
    const float* t0 = tgt + (size_t)b * 3 * MM;
    float cs = 0.f, d0 = 0.f, d1 = 0.f, d2 = 0.f;
    int m0 = tid * 8;
#pragma unroll
    for (int h = 0; h < 2; h++) {
        int m = m0 + h * 4;
        float4 v  = *(const float4*)(p + m);
        float4 ta = *(const float4*)(t0 + m);
        float4 tb = *(const float4*)(t0 + MM + m);
        float4 tc = *(const float4*)(t0 + 2 * MM + m);
        unsigned mk4 = *(const unsigned*)(mtgt + m);
        float vv[4]  = {v.x, v.y, v.z, v.w};
        float taa[4] = {ta.x, ta.y, ta.z, ta.w};
        float tbb[4] = {tb.x, tb.y, tb.z, tb.w};
        float tcc[4] = {tc.x, tc.y, tc.z, tc.w};
#pragma unroll
        for (int i = 0; i < 4; i++) {
            float e = __expf(vv[i] - rm);
            float sc = e * riz;
            bool keep = msrc || ((mk4 >> (8 * i)) & 1) || (e >= 1.0f);
            if (keep) { cs += sc; d0 += sc * taa[i]; d1 += sc * tbb[i]; d2 += sc * tcc[i]; }
        }
    }
#pragma unroll
    for (int o = 16; o > 0; o >>= 1) {
        cs += __shfl_xor_sync(0xffffffffu, cs, o);
        d0 += __shfl_xor_sync(0xffffffffu, d0, o);
        d1 += __shfl_xor_sync(0xffffffffu, d1, o);
        d2 += __shfl_xor_sync(0xffffffffu, d2, o);
    }
    if (lane == 0) { sm[w][0] = cs; sm[w][1] = d0; sm[w][2] = d1; sm[w][3] = d2; }
    __syncthreads();
    if (tid == 0) {
        float C = 0.f, D0 = 0.f, D1 = 0.f, D2 = 0.f;
#pragma unroll
        for (int q = 0; q < 8; q++) { C += sm[q][0]; D0 += sm[q][1]; D1 += sm[q][2]; D2 += sm[q][3]; }
        float denom = C < 1e-5f ? 1e-5f : C;
        float inv = 1.f / denom;
        outCorr[(size_t)(b * 3 + 0) * NN + n] = D0 * inv;
        outCorr[(size_t)(b * 3 + 1) * NN + n] = D1 * inv;
        outCorr[(size_t)(b * 3 + 2) * NN + n] = D2 * inv;
        g_valInlier[row] = msrc ? 0.f : (C * inv);
    }
}

// ---------------- src_weight normalize ----------------
__global__ __launch_bounds__(256) void src_weight_kernel(float* __restrict__ outW) {
    __shared__ float sm[256];
    int b = blockIdx.x, tid = threadIdx.x;
    float s = 0.f;
    for (int i = tid; i < 2048; i += 256) s += g_valInlier[b * 2048 + i];
    sm[tid] = s; __syncthreads();
    for (int st = 128; st > 0; st >>= 1) { if (tid < st) sm[tid] += sm[tid + st]; __syncthreads(); }
    float inv = 1.f / sm[0];
    for (int i = tid; i < 2048; i += 256) outW[b * 2048 + i] = g_valInlier[b * 2048 + i] * inv;
}

// ---------------- launch ----------------
extern "C" void kernel_launch(void* const* d_in, const int* in_sizes, int n_in,
                              void* d_out, int out_size) {
    const float* src_emb = (const float*)d_in[0];
    const float* tgt_emb = (const float*)d_in[1];
    const float* tgt = (const float*)d_in[3];

    float* out = (float*)d_out;
    float* outCorr    = out;
    float* outW       = out + BB * 3 * NN;
    float* outMaskSrc = outW + BB * NN;
    float* outMaskTgt = outMaskSrc + BB * NN;

    // launches 0,1,2 keep the GEMM at profiled slot 3
    sqnorm_kernel<<<(BB * 2048 + 255) / 256, 256>>>(src_emb, 0);
    sqnorm_kernel<<<(BB * 2048 + 255) / 256, 256>>>(tgt_emb, 1);
    nop_kernel<<<1, 32>>>();

    gemm_pd_kernel<<<dim3(MM / 128, NN / 64, BB), 256>>>(src_emb, tgt_emb);

    merge_stats_kernel<<<dim3((BB * 2048 + 255) / 256, 2), 256>>>();

    cs_rs_kernel<<<dim3(2, 32, BB), 256>>>();

    thresh_kernel<<<dim3(BB, 2), 256>>>(outMaskTgt, outMaskSrc);

    final_row_kernel<<<BB * NN, 256>>>(tgt, outCorr);

    src_weight_kernel<<<BB, 256>>>(outW);
}

// round 14
// speedup vs baseline: 2.0520x; 2.0520x over previous
#include <cuda_runtime.h>
#include <cfloat>

#define BB 8
#define CC 64
#define NN 2048
#define MM 2048
#define KSEL 614

typedef unsigned long long ull;

__device__ float g_pd[(size_t)BB * NN * MM];
__device__ float g_xx[BB * NN];
__device__ float g_yy[BB * MM];
__device__ float g_rowp_m[16 * BB * NN];
__device__ float g_rowp_z[16 * BB * NN];
__device__ float g_colp_m[16 * BB * MM];
__device__ float g_colp_z[16 * BB * MM];
__device__ float g_rowmax[BB * NN];
__device__ float g_rowinvZ[BB * NN];
__device__ float g_colmax[BB * MM];
__device__ float g_colinvZ[BB * MM];
__device__ float g_csp[32 * BB * MM];
__device__ float g_rsp[2 * BB * NN];
__device__ unsigned char g_maskSrc[BB * NN];
__device__ unsigned char g_maskTgt[BB * MM];
__device__ float g_valInlier[BB * NN];

// ---------------- f32x2 / cp.async helpers ----------------
__device__ __forceinline__ ull pack2(float x, float y) {
    ull r; asm("mov.b64 %0, {%1, %2};" : "=l"(r) : "f"(x), "f"(y)); return r;
}
__device__ __forceinline__ float2 unpack2(ull v) {
    float2 r; asm("mov.b64 {%0, %1}, %2;" : "=f"(r.x), "=f"(r.y) : "l"(v)); return r;
}
#define FMA2(d, a, b) asm("fma.rn.f32x2 %0, %1, %2, %0;" : "+l"(d) : "l"(a), "l"(b))
#define CP_ASYNC16(saddr, gptr) \
    asm volatile("cp.async.cg.shared.global [%0], [%1], 16;" :: "r"(saddr), "l"(gptr) : "memory")
#define CP_COMMIT() asm volatile("cp.async.commit_group;" ::: "memory")
#define CP_WAIT(n)  asm volatile("cp.async.wait_group %0;" :: "n"(n) : "memory")

// ---------------- squared norms (one tensor per launch) ----------------
__global__ void sqnorm_kernel(const float* __restrict__ emb, int which) {
    int idx = blockIdx.x * blockDim.x + threadIdx.x;
    if (idx >= BB * 2048) return;
    int b = idx >> 11, p = idx & 2047;
    const float* e = emb + (size_t)b * CC * 2048 + p;
    float s = 0.f;
#pragma unroll
    for (int c = 0; c < CC; c++) { float v = e[(size_t)c * 2048]; s += v * v; }
    if (which) g_yy[idx] = s; else g_xx[idx] = s;
}

// ---------------- no-op spacer (keeps GEMM at profiled launch slot 3) -------------
__global__ void nop_kernel() {}

// ---------------- GEMM (FFMA2): 128x128 tile, cp.async double-buffered ------------
__global__ __launch_bounds__(256, 2) void gemm_pd_kernel(const float* __restrict__ src,
                                                         const float* __restrict__ tgt) {
    __shared__ __align__(16) float As[2][16][128];   // 2 x 8KB
    __shared__ __align__(16) float Bs[2][16][128];   // 2 x 8KB

    int b = blockIdx.z;
    int m0 = blockIdx.x * 128, n0 = blockIdx.y * 128;
    int tid = threadIdx.x;
    int tx = tid & 15, ty = tid >> 4;
    const float* Sg = src + (size_t)b * CC * NN + n0;
    const float* Tg = tgt + (size_t)b * CC * MM + m0;

    unsigned sA0 = (unsigned)__cvta_generic_to_shared(&As[0][0][0]);
    unsigned sB0 = (unsigned)__cvta_generic_to_shared(&Bs[0][0][0]);

    ull acc[8][4];
#pragma unroll
    for (int j = 0; j < 8; j++)
#pragma unroll
        for (int i = 0; i < 4; i++) acc[j][i] = 0ull;

    // issue stage s into buffer p: 512 16B units each for A and B
#define ISSUE_STAGE(s, p)                                                              \
    {                                                                                  \
        _Pragma("unroll")                                                              \
        for (int c = 0; c < 2; c++) {                                                  \
            int u = tid + c * 256;                                                     \
            int kr = u >> 5, cu = (u & 31) * 4;                                        \
            CP_ASYNC16(sA0 + (p) * 8192 + u * 16,                                      \
                       Sg + (size_t)(16 * (s) + kr) * NN + cu);                        \
            CP_ASYNC16(sB0 + (p) * 8192 + u * 16,                                      \
                       Tg + (size_t)(16 * (s) + kr) * MM + cu);                        \
        }                                                                              \
        CP_COMMIT();                                                                   \
    }

    ISSUE_STAGE(0, 0);
    ISSUE_STAGE(1, 1);

#pragma unroll
    for (int s = 0; s < 4; s++) {
        if (s < 3) CP_WAIT(1); else CP_WAIT(0);
        __syncthreads();
        int buf = s & 1;
#pragma unroll
        for (int k = 0; k < 16; k++) {
            float4 a4a = *(const float4*)&As[buf][k][ty * 8];
            float4 a4b = *(const float4*)&As[buf][k][ty * 8 + 4];
            ull bv[4];
            *(ulonglong2*)&bv[0] = *(const ulonglong2*)&Bs[buf][k][tx * 8];
            *(ulonglong2*)&bv[2] = *(const ulonglong2*)&Bs[buf][k][tx * 8 + 4];
            ull a[8];
            a[0] = pack2(a4a.x, a4a.x); a[1] = pack2(a4a.y, a4a.y);
            a[2] = pack2(a4a.z, a4a.z); a[3] = pack2(a4a.w, a4a.w);
            a[4] = pack2(a4b.x, a4b.x); a[5] = pack2(a4b.y, a4b.y);
            a[6] = pack2(a4b.z, a4b.z); a[7] = pack2(a4b.w, a4b.w);
#pragma unroll
            for (int j = 0; j < 8; j++) {
                FMA2(acc[j][0], a[j], bv[0]);
                FMA2(acc[j][1], a[j], bv[1]);
                FMA2(acc[j][2], a[j], bv[2]);
                FMA2(acc[j][3], a[j], bv[3]);
            }
        }
        __syncthreads();
        if (s < 2) ISSUE_STAGE(s + 2, buf);
    }

    // ---- epilogue: finalize pd, write, fused TRUE row/col stat partials ----
    int cg = m0 + tx * 8;
    float yv[8], xr[8];
    *(float4*)&yv[0] = *(const float4*)&g_yy[b * MM + cg];
    *(float4*)&yv[4] = *(const float4*)&g_yy[b * MM + cg + 4];
#pragma unroll
    for (int j = 0; j < 8; j++) xr[j] = g_xx[b * NN + n0 + ty * 8 + j];

    float cm[8];
#pragma unroll
    for (int i = 0; i < 8; i++) cm[i] = -FLT_MAX;
#pragma unroll
    for (int j = 0; j < 8; j++) {
#pragma unroll
        for (int i = 0; i < 4; i++) {
            float2 p = unpack2(acc[j][i]);
            cm[2 * i]     = fmaxf(cm[2 * i],     2.f * p.x - xr[j] - yv[2 * i]);
            cm[2 * i + 1] = fmaxf(cm[2 * i + 1], 2.f * p.y - xr[j] - yv[2 * i + 1]);
        }
    }

    float colz[8];
#pragma unroll
    for (int i = 0; i < 8; i++) colz[i] = 0.f;
#pragma unroll
    for (int j = 0; j < 8; j++) {
        float fr[8];
#pragma unroll
        for (int i = 0; i < 4; i++) {
            float2 p = unpack2(acc[j][i]);
            fr[2 * i]     = 2.f * p.x - xr[j] - yv[2 * i];
            fr[2 * i + 1] = 2.f * p.y - xr[j] - yv[2 * i + 1];
        }
        int n = n0 + ty * 8 + j;
        float* prow = g_pd + (size_t)(b * NN + n) * MM;
        *(float4*)&prow[cg]     = make_float4(fr[0], fr[1], fr[2], fr[3]);
        *(float4*)&prow[cg + 4] = make_float4(fr[4], fr[5], fr[6], fr[7]);

        float rmx = fr[0];
#pragma unroll
        for (int i = 1; i < 8; i++) rmx = fmaxf(rmx, fr[i]);
#pragma unroll
        for (int o = 1; o < 16; o <<= 1) rmx = fmaxf(rmx, __shfl_xor_sync(0xffffffffu, rmx, o));
        float rz = 0.f;
#pragma unroll
        for (int i = 0; i < 8; i++) rz += __expf(fr[i] - rmx);
#pragma unroll
        for (int o = 1; o < 16; o <<= 1) rz += __shfl_xor_sync(0xffffffffu, rz, o);
        if (tx == 0) {
            g_rowp_m[blockIdx.x * (BB * NN) + b * NN + n] = rmx;
            g_rowp_z[blockIdx.x * (BB * NN) + b * NN + n] = rz;
        }
#pragma unroll
        for (int i = 0; i < 8; i++) colz[i] += __expf(fr[i] - cm[i]);
    }

    __syncthreads();
    float* sm_m = &As[0][0][0];            // [16][128] = 8KB (reuse)
    float* sm_z = &As[1][0][0];            // 8KB
#pragma unroll
    for (int i = 0; i < 8; i++) {
        sm_m[ty * 128 + tx * 8 + i] = cm[i];
        sm_z[ty * 128 + tx * 8 + i] = colz[i];
    }
    __syncthreads();
    if (tid < 128) {
        int c = tid;
        float M = -FLT_MAX;
#pragma unroll
        for (int t = 0; t < 16; t++) M = fmaxf(M, sm_m[t * 128 + c]);
        float Z = 0.f;
#pragma unroll
        for (int t = 0; t < 16; t++) Z += sm_z[t * 128 + c] * __expf(sm_m[t * 128 + c] - M);
        g_colp_m[blockIdx.y * (BB * MM) + b * MM + m0 + c] = M;
        g_colp_z[blockIdx.y * (BB * MM) + b * MM + m0 + c] = Z;
    }
}

// ---------------- merge stat partials ----------------
__global__ void merge_stats_kernel() {
    int idx = blockIdx.x * blockDim.x + threadIdx.x;
    if (idx >= BB * 2048) return;
    if (blockIdx.y == 0) {
        float M = -FLT_MAX, Z = 0.f;
#pragma unroll
        for (int t = 0; t < 16; t++) {
            float m2 = g_rowp_m[t * (BB * NN) + idx], z2 = g_rowp_z[t * (BB * NN) + idx];
            float nm = fmaxf(M, m2);
            Z = Z * __expf(M - nm) + z2 * __expf(m2 - nm);
            M = nm;
        }
        g_rowmax[idx] = M; g_rowinvZ[idx] = 1.f / Z;
    } else {
        float M = -FLT_MAX, Z = 0.f;
#pragma unroll
        for (int t = 0; t < 16; t++) {
            float m2 = g_colp_m[t * (BB * MM) + idx], z2 = g_colp_z[t * (BB * MM) + idx];
            float nm = fmaxf(M, m2);
            Z = Z * __expf(M - nm) + z2 * __expf(m2 - nm);
            M = nm;
        }
        g_colmax[idx] = M; g_colinvZ[idx] = 1.f / Z;
    }
}

// ---------------- fused colSum + rowSum pass: 1024 cols x 64 rows, 512 blocks ------
__global__ __launch_bounds__(256) void cs_rs_kernel() {
    __shared__ float s_rm[64], s_riz[64];
    __shared__ float rs_w[8][64];
    int b = blockIdx.z, rt = blockIdx.y, ct = blockIdx.x;
    int tid = threadIdx.x, lane = tid & 31, warp = tid >> 5;
    int m = ct * 1024 + tid * 4;
    int r0 = rt * 64;
    if (tid < 64) {
        s_rm[tid]  = g_rowmax[b * NN + r0 + tid];
        s_riz[tid] = g_rowinvZ[b * NN + r0 + tid];
    }
    float4 cmx = *(const float4*)&g_colmax[b * MM + m];
    float4 ciz = *(const float4*)&g_colinvZ[b * MM + m];
    __syncthreads();
    float cs0 = 0.f, cs1 = 0.f, cs2 = 0.f, cs3 = 0.f;
    const float* base = g_pd + ((size_t)(b * NN + r0)) * MM + m;
    for (int g = 0; g < 16; g++) {
        float rs[4];
#pragma unroll
        for (int u = 0; u < 4; u++) {
            int n = g * 4 + u;
            float4 v = *(const float4*)(base + (size_t)n * MM);
            float rm = s_rm[n], riz = s_riz[n];
            cs0 += __expf(v.x - rm) * riz; cs1 += __expf(v.y - rm) * riz;
            cs2 += __expf(v.z - rm) * riz; cs3 += __expf(v.w - rm) * riz;
            rs[u] = __expf(v.x - cmx.x) * ciz.x + __expf(v.y - cmx.y) * ciz.y
                  + __expf(v.z - cmx.z) * ciz.z + __expf(v.w - cmx.w) * ciz.w;
        }
#pragma unroll
        for (int o = 16; o > 0; o >>= 1) {
            rs[0] += __shfl_xor_sync(0xffffffffu, rs[0], o);
            rs[1] += __shfl_xor_sync(0xffffffffu, rs[1], o);
            rs[2] += __shfl_xor_sync(0xffffffffu, rs[2], o);
            rs[3] += __shfl_xor_sync(0xffffffffu, rs[3], o);
        }
        if (lane == 0) {
            rs_w[warp][g * 4]     = rs[0];
            rs_w[warp][g * 4 + 1] = rs[1];
            rs_w[warp][g * 4 + 2] = rs[2];
            rs_w[warp][g * 4 + 3] = rs[3];
        }
    }
    __syncthreads();
    *(float4*)&g_csp[rt * (BB * MM) + b * MM + m] = make_float4(cs0, cs1, cs2, cs3);
    if (tid < 64) {
        float s = 0.f;
#pragma unroll
        for (int q = 0; q < 8; q++) s += rs_w[q][tid];
        g_rsp[ct * (BB * NN) + b * NN + r0 + tid] = s;
    }
}

// ---------------- per-batch k-th smallest ----------------
__global__ __launch_bounds__(256) void thresh_kernel(float* __restrict__ outMaskTgt,
                                                     float* __restrict__ outMaskSrc) {
    __shared__ float s[2048];
    __shared__ float vals[2048];
    int b = blockIdx.x, which = blockIdx.y, tid = threadIdx.x;
    if (which == 0) {
        for (int i = tid; i < 2048; i += 256) {
            float v = 0.f;
#pragma unroll
            for (int t = 0; t < 32; t++) v += g_csp[t * (BB * MM) + b * MM + i];
            vals[i] = v; s[i] = v;
        }
    } else {
        for (int i = tid; i < 2048; i += 256) {
            float v = g_rsp[b * NN + i] + g_rsp[BB * NN + b * NN + i];
            vals[i] = v; s[i] = v;
        }
    }
    __syncthreads();
    for (int k = 2; k <= 2048; k <<= 1) {
        for (int j = k >> 1; j > 0; j >>= 1) {
            for (int t = tid; t < 2048; t += 256) {
                int ixj = t ^ j;
                if (ixj > t) {
                    float a = s[t], c = s[ixj];
                    bool up = ((t & k) == 0);
                    if (up ? (a > c) : (a < c)) { s[t] = c; s[ixj] = a; }
                }
            }
            __syncthreads();
        }
    }
    float thresh = s[KSEL - 1];
    unsigned char* mb = which ? (g_maskSrc + b * 2048) : (g_maskTgt + b * 2048);
    float* mf = (which ? outMaskSrc : outMaskTgt) + b * 2048;
    for (int i = tid; i < 2048; i += 256) {
        bool mk = vals[i] < thresh;
        mb[i] = (unsigned char)mk;
        mf[i] = mk ? 1.0f : 0.0f;
    }
}

// ---------------- final row pass (R8 form) ----------------
__global__ __launch_bounds__(256) void final_row_kernel(const float* __restrict__ tgt,
                                                        float* __restrict__ outCorr) {
    __shared__ float sm[8][4];
    int row = blockIdx.x;
    int b = row >> 11, n = row & 2047;
    int tid = threadIdx.x, lane = tid & 31, w = tid >> 5;
    const float* p = g_pd + (size_t)row * MM;
    float rm = g_rowmax[row], riz = g_rowinvZ[row];
    int msrc = g_maskSrc[row];
    const unsigned char* mtgt = g_maskTgt + b * MM;
    const float* t0 = tgt + (size_t)b * 3 * MM;
    float cs = 0.f, d0 = 0.f, d1 = 0.f, d2 = 0.f;
    int m0 = tid * 8;
#pragma unroll
    for (int h = 0; h < 2; h++) {
        int m = m0 + h * 4;
        float4 v  = *(const float4*)(p + m);
        float4 ta = *(const float4*)(t0 + m);
        float4 tb = *(const float4*)(t0 + MM + m);
        float4 tc = *(const float4*)(t0 + 2 * MM + m);
        unsigned mk4 = *(const unsigned*)(mtgt + m);
        float vv[4]  = {v.x, v.y, v.z, v.w};
        float taa[4] = {ta.x, ta.y, ta.z, ta.w};
        float tbb[4] = {tb.x, tb.y, tb.z, tb.w};
        float tcc[4] = {tc.x, tc.y, tc.z, tc.w};
#pragma unroll
        for (int i = 0; i < 4; i++) {
            float e = __expf(vv[i] - rm);
            float sc = e * riz;
            bool keep = msrc || ((mk4 >> (8 * i)) & 1) || (e >= 1.0f);
            if (keep) { cs += sc; d0 += sc * taa[i]; d1 += sc * tbb[i]; d2 += sc * tcc[i]; }
        }
    }
#pragma unroll
    for (int o = 16; o > 0; o >>= 1) {
        cs += __shfl_xor_sync(0xffffffffu, cs, o);
        d0 += __shfl_xor_sync(0xffffffffu, d0, o);
        d1 += __shfl_xor_sync(0xffffffffu, d1, o);
        d2 += __shfl_xor_sync(0xffffffffu, d2, o);
    }
    if (lane == 0) { sm[w][0] = cs; sm[w][1] = d0; sm[w][2] = d1; sm[w][3] = d2; }
    __syncthreads();
    if (tid == 0) {
        float C = 0.f, D0 = 0.f, D1 = 0.f, D2 = 0.f;
#pragma unroll
        for (int q = 0; q < 8; q++) { C += sm[q][0]; D0 += sm[q][1]; D1 += sm[q][2]; D2 += sm[q][3]; }
        float denom = C < 1e-5f ? 1e-5f : C;
        float inv = 1.f / denom;
        outCorr[(size_t)(b * 3 + 0) * NN + n] = D0 * inv;
        outCorr[(size_t)(b * 3 + 1) * NN + n] = D1 * inv;
        outCorr[(size_t)(b * 3 + 2) * NN + n] = D2 * inv;
        g_valInlier[row] = msrc ? 0.f : (C * inv);
    }
}

// ---------------- src_weight normalize ----------------
__global__ __launch_bounds__(256) void src_weight_kernel(float* __restrict__ outW) {
    __shared__ float sm[256];
    int b = blockIdx.x, tid = threadIdx.x;
    float s = 0.f;
    for (int i = tid; i < 2048; i += 256) s += g_valInlier[b * 2048 + i];
    sm[tid] = s; __syncthreads();
    for (int st = 128; st > 0; st >>= 1) { if (tid < st) sm[tid] += sm[tid + st]; __syncthreads(); }
    float inv = 1.f / sm[0];
    for (int i = tid; i < 2048; i += 256) outW[b * 2048 + i] = g_valInlier[b * 2048 + i] * inv;
}

// ---------------- launch ----------------
extern "C" void kernel_launch(void* const* d_in, const int* in_sizes, int n_in,
                              void* d_out, int out_size) {
    const float* src_emb = (const float*)d_in[0];
    const float* tgt_emb = (const float*)d_in[1];
    const float* tgt = (const float*)d_in[3];

    float* out = (float*)d_out;
    float* outCorr    = out;
    float* outW       = out + BB * 3 * NN;
    float* outMaskSrc = outW + BB * NN;
    float* outMaskTgt = outMaskSrc + BB * NN;

    // launches 0,1,2 keep the GEMM at profiled slot 3
    sqnorm_kernel<<<(BB * 2048 + 255) / 256, 256>>>(src_emb, 0);
    sqnorm_kernel<<<(BB * 2048 + 255) / 256, 256>>>(tgt_emb, 1);
    nop_kernel<<<1, 32>>>();

    gemm_pd_kernel<<<dim3(MM / 128, NN / 128, BB), 256>>>(src_emb, tgt_emb);

    merge_stats_kernel<<<dim3((BB * 2048 + 255) / 256, 2), 256>>>();

    cs_rs_kernel<<<dim3(2, 32, BB), 256>>>();

    thresh_kernel<<<dim3(BB, 2), 256>>>(outMaskTgt, outMaskSrc);

    final_row_kernel<<<BB * NN, 256>>>(tgt, outCorr);

    src_weight_kernel<<<BB, 256>>>(outW);
}